// round 9
// baseline (speedup 1.0000x reference)
#include <cuda_runtime.h>

#define BB   8
#define DIMM 1024
#define TQ   2048
#define CDD  128
#define KK   1024
#define QQ   8
#define BT   (BB*TQ)   // 16384

// ---- scratch (device globals) ----
__device__ float g_H[QQ*CDD*BT];                 // 64 MB  h for all q [q][c][bt], corrected in-place
__device__ float g_cT[QQ*CDD*BT];                // 64 MB  chosen codes [q][c][bt]
__device__ float g_et[QQ*CDD*KK];                // 4 MB   E transposed [q][c][k]
__device__ float g_e2[QQ*KK];                    // ||E_k||^2
__device__ float g_woT[QQ*DIMM*CDD];             // 4 MB   Wout transposed [q][d][c]
__device__ float g_M[QQ*QQ*CDD*CDD];             // 4 MB   M[j][q'] = Wout_j . Win_q'
__device__ float g_Mp[8*QQ*QQ*CDD*CDD];          // 32 MB  split-d partials
__device__ unsigned long long g_part[4*BT];      // per-split argmin packs
__device__ float g_Pb[QQ*DIMM];                  // prefix sums of bout
__device__ float g_sb[DIMM];                     // total bout sum
__device__ float g_bv[QQ*CDD];                   // (prefix bout).Win_q

// ---- packed f32x2 helpers ----
static __device__ __forceinline__ unsigned long long pk2(float v) {
    unsigned long long r; unsigned int u = __float_as_uint(v);
    asm("mov.b64 %0, {%1, %1};" : "=l"(r) : "r"(u));
    return r;
}
static __device__ __forceinline__ void fma2(unsigned long long& d,
                                            unsigned long long a, unsigned long long b) {
    asm("fma.rn.f32x2 %0, %1, %2, %0;" : "+l"(d) : "l"(a), "l"(b));
}
static __device__ __forceinline__ float2 unpk2(unsigned long long v) {
    unsigned int lo, hi;
    asm("mov.b64 {%0, %1}, %2;" : "=r"(lo), "=r"(hi) : "l"(v));
    float2 f; f.x = __uint_as_float(lo); f.y = __uint_as_float(hi);
    return f;
}
static __device__ __forceinline__ void cpa16(void* s, const void* g) {
    unsigned int sa = (unsigned int)__cvta_generic_to_shared(s);
    asm volatile("cp.async.cg.shared.global [%0], [%1], 16;" :: "r"(sa), "l"(g));
}
#define CP_COMMIT asm volatile("cp.async.commit_group;")
#define CP_WAIT0  asm volatile("cp.async.wait_group 0;")

// 8 scalar rows x 8 packed cols (v0,v1 ulonglong2) -> 32 FFMA2
#define FMA2_ROW(i, s) { unsigned long long p = pk2(s); \
    fma2(acc[i][0], p, v0.x); fma2(acc[i][1], p, v0.y); \
    fma2(acc[i][2], p, v1.x); fma2(acc[i][3], p, v1.y); }
#define MICRO8(S0, S1) do { \
    FMA2_ROW(0, S0.x); FMA2_ROW(1, S0.y); FMA2_ROW(2, S0.z); FMA2_ROW(3, S0.w); \
    FMA2_ROW(4, S1.x); FMA2_ROW(5, S1.y); FMA2_ROW(6, S1.z); FMA2_ROW(7, S1.w); } while (0)

// 8 scalar cols x 4 packed-t -> 16 FFMA2 (k_corr)
#define MICRO4x8(w0, w1) do { unsigned long long p; \
    p = pk2(w0.x); fma2(acc[0][0], p, v.x); fma2(acc[0][1], p, v.y); \
    p = pk2(w0.y); fma2(acc[1][0], p, v.x); fma2(acc[1][1], p, v.y); \
    p = pk2(w0.z); fma2(acc[2][0], p, v.x); fma2(acc[2][1], p, v.y); \
    p = pk2(w0.w); fma2(acc[3][0], p, v.x); fma2(acc[3][1], p, v.y); \
    p = pk2(w1.x); fma2(acc[4][0], p, v.x); fma2(acc[4][1], p, v.y); \
    p = pk2(w1.y); fma2(acc[5][0], p, v.x); fma2(acc[5][1], p, v.y); \
    p = pk2(w1.z); fma2(acc[6][0], p, v.x); fma2(acc[6][1], p, v.y); \
    p = pk2(w1.w); fma2(acc[7][0], p, v.x); fma2(acc[7][1], p, v.y); } while (0)

// ---- per-code squared norms ----
__global__ void k_e2(const float* __restrict__ E) {
    int row  = blockIdx.x * (blockDim.x >> 5) + (threadIdx.x >> 5);
    int lane = threadIdx.x & 31;
    if (row >= QQ * KK) return;
    const float* e = E + (size_t)row * CDD;
    float4 v = *(const float4*)(e + lane * 4);
    float s = v.x*v.x + v.y*v.y + v.z*v.z + v.w*v.w;
    #pragma unroll
    for (int o = 16; o; o >>= 1) s += __shfl_xor_sync(0xffffffffu, s, o);
    if (lane == 0) g_e2[row] = s;
}

// ---- E transpose: g_et[q][c][k] = E[q][k][c] ----
__global__ void k_et(const float* __restrict__ E) {
    __shared__ float tile[32][33];
    int q = blockIdx.z, k0 = blockIdx.x * 32, c0 = blockIdx.y * 32;
    int tx = threadIdx.x & 31, ty = threadIdx.x >> 5;
    const float* Eq = E + (size_t)q * KK * CDD;
    #pragma unroll
    for (int i = 0; i < 4; i++)
        tile[ty + 8*i][tx] = Eq[(size_t)(k0 + ty + 8*i) * CDD + c0 + tx];
    __syncthreads();
    float* o = g_et + (size_t)q * CDD * KK;
    #pragma unroll
    for (int i = 0; i < 4; i++)
        o[(size_t)(c0 + ty + 8*i) * KK + k0 + tx] = tile[tx][ty + 8*i];
}

// ---- Wout transpose: g_woT[q][d][c] = Wout[q][c][d] ----
__global__ void k_woT(const float* __restrict__ Wout) {
    __shared__ float tile[32][33];
    int q = blockIdx.z, d0 = blockIdx.x * 32, c0 = blockIdx.y * 32;
    int tx = threadIdx.x & 31, ty = threadIdx.x >> 5;
    const float* Wq = Wout + (size_t)q * CDD * DIMM;
    #pragma unroll
    for (int i = 0; i < 4; i++)
        tile[ty + 8*i][tx] = Wq[(size_t)(c0 + ty + 8*i) * DIMM + d0 + tx];
    __syncthreads();
    float* o = g_woT + (size_t)q * DIMM * CDD;
    #pragma unroll
    for (int i = 0; i < 4; i++)
        o[(size_t)(d0 + ty + 8*i) * CDD + c0 + tx] = tile[tx][ty + 8*i];
}

// ---- bias prep: prefix sums of bout + total ----
__global__ void k_pb(const float* __restrict__ bout) {
    int d = blockIdx.x * 256 + threadIdx.x;
    float run = 0.f;
    #pragma unroll
    for (int j = 0; j < QQ; j++) { g_Pb[j * DIMM + d] = run; run += bout[j * DIMM + d]; }
    g_sb[d] = run;
}
// g_bv[q][c] = sum_d Pb[q][d] * Win[q][d][c]
__global__ void k_bv(const float* __restrict__ Win) {
    int q = blockIdx.x, c = threadIdx.x;
    const float* Wq = Win + (size_t)q * DIMM * CDD;
    float acc = 0.f;
    for (int d = 0; d < DIMM; d++) acc = fmaf(g_Pb[q * DIMM + d], Wq[(size_t)d * CDD + c], acc);
    g_bv[q * CDD + c] = acc;
}

// ---- M partials: g_Mp[ds][j][qp][c][c'] = sum_{d in slice} woT[j][d][c]*Win[qp][d][c'] ----
// grid (8 qp, 8 j, 8 ds), 256 thr, only j<qp computed.
__global__ void __launch_bounds__(256) k_Mp(const float* __restrict__ Win) {
    __shared__ __align__(16) float As[2][16][128];   // woT slice [d][c]
    __shared__ __align__(16) float Bs[2][16][128];   // Win slice [d][c']
    int qp = blockIdx.x, j = blockIdx.y, ds = blockIdx.z;
    if (j >= qp) return;
    int tid = threadIdx.x, txt = tid & 15, tyc = tid >> 4;
    const float* A = g_woT + (size_t)j  * DIMM * CDD + (size_t)ds * 128 * CDD;
    const float* Bw = Win  + (size_t)qp * DIMM * CDD + (size_t)ds * 128 * CDD;

    #pragma unroll
    for (int j2 = 0; j2 < 2; j2++) { int c4 = tid + j2*256; int dd = c4 >> 5, cc = (c4 & 31)*4;
        cpa16(&As[0][dd][cc], A  + (size_t)dd * CDD + cc);
        cpa16(&Bs[0][dd][cc], Bw + (size_t)dd * CDD + cc); }
    CP_COMMIT;

    unsigned long long acc[8][4];
    #pragma unroll
    for (int i = 0; i < 8; i++)
        #pragma unroll
        for (int p = 0; p < 4; p++) acc[i][p] = 0ull;

    int buf = 0;
    for (int s = 0; s < 8; s++) {
        CP_WAIT0; __syncthreads();
        if (s + 1 < 8) { int d0 = (s + 1) * 16, nb = buf ^ 1;
            #pragma unroll
            for (int j2 = 0; j2 < 2; j2++) { int c4 = tid + j2*256; int dd = c4 >> 5, cc = (c4 & 31)*4;
                cpa16(&As[nb][dd][cc], A  + (size_t)(d0 + dd) * CDD + cc);
                cpa16(&Bs[nb][dd][cc], Bw + (size_t)(d0 + dd) * CDD + cc); }
            CP_COMMIT; }
        #pragma unroll
        for (int dd = 0; dd < 16; dd++) {
            ulonglong2 v0 = *(const ulonglong2*)&Bs[buf][dd][txt * 8];
            ulonglong2 v1 = *(const ulonglong2*)&Bs[buf][dd][txt * 8 + 4];
            float4 a0 = *(const float4*)&As[buf][dd][tyc * 8];
            float4 a1 = *(const float4*)&As[buf][dd][tyc * 8 + 4];
            MICRO8(a0, a1);
        }
        buf ^= 1;
    }
    float* o = g_Mp + ((size_t)(ds * 64 + j * 8 + qp) * CDD) * CDD;
    #pragma unroll
    for (int ci = 0; ci < 8; ci++) {
        int c = tyc * 8 + ci;
        float2 u0 = unpk2(acc[ci][0]), u1 = unpk2(acc[ci][1]);
        float2 u2 = unpk2(acc[ci][2]), u3 = unpk2(acc[ci][3]);
        *(float4*)(o + (size_t)c * CDD + txt * 8)     = make_float4(u0.x, u0.y, u1.x, u1.y);
        *(float4*)(o + (size_t)c * CDD + txt * 8 + 4) = make_float4(u2.x, u2.y, u3.x, u3.y);
    }
}

// ---- M reduce over 8 d-slices (fixed order) ----
__global__ void k_Mred() {
    size_t i = (size_t)blockIdx.x * 256 + threadIdx.x;   // float4 index
    const float4* p = (const float4*)g_Mp;
    float4 a = p[i];
    #pragma unroll
    for (int ds = 1; ds < 8; ds++) {
        float4 v = p[(size_t)ds * (QQ*QQ*CDD*CDD/4) + i];
        a.x += v.x; a.y += v.y; a.z += v.z; a.w += v.w;
    }
    ((float4*)g_M)[i] = a;
}

// ---- H0 for all q: g_H[q][c][bt] = emb.Win_q + bin_q - bv_q ----
// grid (16 tt, 8 b, 8 q), 256 thr. tile 128t x 128c, ktile 16, micro 8t x 8c.
__global__ void __launch_bounds__(256) k_H0(const float* __restrict__ emb,
                                            const float* __restrict__ Win,
                                            const float* __restrict__ bin) {
    __shared__ __align__(16) float As[2][16][128];   // [d][t] 16KB
    __shared__ __align__(16) float Bs[2][16][128];   // [d][c] 16KB
    int t0 = blockIdx.x * 128, b = blockIdx.y, q = blockIdx.z;
    int tid = threadIdx.x, txt = tid & 15, tyc = tid >> 4;
    int bt0 = b * TQ + t0;
    const float* eb = emb + (size_t)b * DIMM * TQ + t0;
    const float* Wq = Win + (size_t)q * DIMM * CDD;

    #pragma unroll
    for (int j2 = 0; j2 < 2; j2++) { int c4 = tid + j2*256; int dd = c4 >> 5, x4 = (c4 & 31)*4;
        cpa16(&As[0][dd][x4], eb + (size_t)dd * TQ + x4);
        cpa16(&Bs[0][dd][x4], Wq + (size_t)dd * CDD + x4); }
    CP_COMMIT;

    unsigned long long acc[8][4];
    #pragma unroll
    for (int i = 0; i < 8; i++)
        #pragma unroll
        for (int p = 0; p < 4; p++) acc[i][p] = 0ull;

    int buf = 0;
    for (int s = 0; s < 64; s++) {
        CP_WAIT0; __syncthreads();
        if (s + 1 < 64) { int d0 = (s + 1) * 16, nb = buf ^ 1;
            #pragma unroll
            for (int j2 = 0; j2 < 2; j2++) { int c4 = tid + j2*256; int dd = c4 >> 5, x4 = (c4 & 31)*4;
                cpa16(&As[nb][dd][x4], eb + (size_t)(d0 + dd) * TQ + x4);
                cpa16(&Bs[nb][dd][x4], Wq + (size_t)(d0 + dd) * CDD + x4); }
            CP_COMMIT; }
        #pragma unroll
        for (int dd = 0; dd < 16; dd++) {
            ulonglong2 v0 = *(const ulonglong2*)&As[buf][dd][txt * 8];
            ulonglong2 v1 = *(const ulonglong2*)&As[buf][dd][txt * 8 + 4];
            float4 w0 = *(const float4*)&Bs[buf][dd][tyc * 8];
            float4 w1 = *(const float4*)&Bs[buf][dd][tyc * 8 + 4];
            MICRO8(w0, w1);
        }
        buf ^= 1;
    }
    #pragma unroll
    for (int ci = 0; ci < 8; ci++) {
        int c = tyc * 8 + ci;
        float bi = bin[q * CDD + c] - g_bv[q * CDD + c];
        float2 u0 = unpk2(acc[ci][0]), u1 = unpk2(acc[ci][1]);
        float2 u2 = unpk2(acc[ci][2]), u3 = unpk2(acc[ci][3]);
        float* hp = g_H + ((size_t)q * CDD + c) * BT + bt0 + txt * 8;
        *(float4*)hp       = make_float4(u0.x + bi, u0.y + bi, u1.x + bi, u1.y + bi);
        *(float4*)(hp + 4) = make_float4(u2.x + bi, u2.y + bi, u3.x + bi, u3.y + bi);
    }
}

// ---- dist+argmin: grid (256, 4), 128 thr; writes per-split packed min ----
#define ES_PREFETCH(bufi, n0, c0) do { \
    _Pragma("unroll") for (int j = 0; j < 4; j++) { int c4 = tid + j*128; \
        int cc = c4 >> 5, kk = (c4 & 31) * 4; \
        cpa16(&Es[bufi][cc][kk], etq + (size_t)((c0) + cc) * KK + (n0) + kk); } \
    CP_COMMIT; } while (0)

__global__ void __launch_bounds__(128) k_dist(int q) {
    __shared__ __align__(16) float hsT[128][64];    // 32KB
    __shared__ __align__(16) float Es[2][16][128];  // 16KB
    __shared__ unsigned long long red[64][16];      // 8KB
    int r0 = blockIdx.x * 64, nbase = blockIdx.y * 256;
    int tid = threadIdx.x, txt = tid & 7, tyk = tid >> 3;
    const float* etq = g_et + (size_t)q * CDD * KK;
    const float* e2q = g_e2 + q * KK;
    const float* hq  = g_H + (size_t)q * CDD * BT;

    float e2r[2][8];
    #pragma unroll
    for (int nt = 0; nt < 2; nt++) {
        float4 a = *(const float4*)(e2q + nbase + nt * 128 + tyk * 8);
        float4 c = *(const float4*)(e2q + nbase + nt * 128 + tyk * 8 + 4);
        e2r[nt][0] = a.x; e2r[nt][1] = a.y; e2r[nt][2] = a.z; e2r[nt][3] = a.w;
        e2r[nt][4] = c.x; e2r[nt][5] = c.y; e2r[nt][6] = c.z; e2r[nt][7] = c.w;
    }
    #pragma unroll
    for (int j = 0; j < 16; j++) { int c4 = tid + j*128; int c = c4 >> 4, t4 = (c4 & 15) * 4;
        cpa16(&hsT[c][t4], hq + (size_t)c * BT + r0 + t4); }
    ES_PREFETCH(0, nbase, 0);

    float minv[8]; int mini[8];
    #pragma unroll
    for (int j = 0; j < 8; j++) { minv[j] = 3.0e38f; mini[j] = 0; }
    unsigned long long acc[8][4];
    int buf = 0;
    for (int s = 0; s < 16; s++) {
        CP_WAIT0; __syncthreads();
        if (s + 1 < 16) { int s1 = s + 1;
            ES_PREFETCH(buf ^ 1, nbase + (s1 >> 3) * 128, (s1 & 7) * 16); }
        if ((s & 7) == 0) {
            #pragma unroll
            for (int i = 0; i < 8; i++)
                #pragma unroll
                for (int j = 0; j < 4; j++) acc[i][j] = 0ull;
        }
        int c0 = (s & 7) * 16;
        #pragma unroll 8
        for (int cc = 0; cc < 16; cc++) {
            ulonglong2 v0 = *(const ulonglong2*)&hsT[c0 + cc][txt * 8];
            ulonglong2 v1 = *(const ulonglong2*)&hsT[c0 + cc][txt * 8 + 4];
            float4 e0 = *(const float4*)&Es[buf][cc][tyk * 8];
            float4 e1 = *(const float4*)&Es[buf][cc][tyk * 8 + 4];
            MICRO8(e0, e1);
        }
        if ((s & 7) == 7) {
            int nt = s >> 3;
            int kb = nbase + nt * 128 + tyk * 8;
            #pragma unroll
            for (int ki = 0; ki < 8; ki++) {
                float ev = e2r[nt][ki];
                int k = kb + ki;
                #pragma unroll
                for (int tp = 0; tp < 4; tp++) {
                    float2 u = unpk2(acc[ki][tp]);
                    float da = ev - 2.0f * u.x;
                    float db = ev - 2.0f * u.y;
                    if (da < minv[tp*2])     { minv[tp*2]     = da; mini[tp*2]     = k; }
                    if (db < minv[tp*2 + 1]) { minv[tp*2 + 1] = db; mini[tp*2 + 1] = k; }
                }
            }
        }
        buf ^= 1;
    }
    #pragma unroll
    for (int j = 0; j < 8; j++) {
        unsigned int bbits = __float_as_uint(minv[j]);
        bbits = (bbits & 0x80000000u) ? ~bbits : (bbits | 0x80000000u);
        red[txt * 8 + j][tyk] = ((unsigned long long)bbits << 32) | (unsigned int)mini[j];
    }
    __syncthreads();
    if (tid < 64) {
        unsigned long long m = red[tid][0];
        #pragma unroll
        for (int x = 1; x < 16; x++) { unsigned long long v = red[tid][x]; if (v < m) m = v; }
        g_part[(size_t)blockIdx.y * BT + r0 + tid] = m;
    }
}

// ---- merge 4 splits + gather codes: g_cT[q][c][bt] = E_q[idx[bt]][c] ----
__global__ void __launch_bounds__(128) k_gather(const float* __restrict__ E, int q) {
    __shared__ float sT[128][65];
    __shared__ int sidx[64];
    int bt0 = blockIdx.x * 64;
    int tid = threadIdx.x;
    if (tid < 64) {
        unsigned long long m = g_part[bt0 + tid];
        #pragma unroll
        for (int s = 1; s < 4; s++) {
            unsigned long long v = g_part[(size_t)s * BT + bt0 + tid];
            if (v < m) m = v;
        }
        sidx[tid] = (int)(unsigned int)(m & 0xFFFFFFFFull);
    }
    __syncthreads();
    const float* Eq = E + (size_t)q * KK * CDD;
    #pragma unroll
    for (int j = 0; j < 16; j++) {
        int ch = tid + j * 128; int tt = ch >> 5, c4 = ch & 31;
        float4 v = *(const float4*)(Eq + (size_t)sidx[tt] * CDD + c4 * 4);
        sT[c4*4][tt] = v.x; sT[c4*4+1][tt] = v.y; sT[c4*4+2][tt] = v.z; sT[c4*4+3][tt] = v.w;
    }
    __syncthreads();
    float* o = g_cT + (size_t)q * CDD * BT;
    #pragma unroll
    for (int j = 0; j < 16; j++) {
        int ch = tid + j * 128; int c = ch >> 4, t4 = (ch & 15) * 4;
        *(float4*)(o + (size_t)c * BT + bt0 + t4) =
            make_float4(sT[c][t4], sT[c][t4+1], sT[c][t4+2], sT[c][t4+3]);
    }
}

// ---- correction: g_H[q'][c'][bt] -= sum_c g_cT[j][c][bt]*M[j][q'][c][c'] ----
// grid (512 bt-tiles, 7-j), 128 thr. tile 32bt x 128c', ktile 32, micro 4t x 8c'.
#define CORR_PREFETCH(bufi, c0) do { \
    _Pragma("unroll") for (int j2 = 0; j2 < 2; j2++) { int c4 = tid + j2*128; \
        int dd = c4 >> 3, t4 = (c4 & 7) * 4; \
        cpa16(&As[bufi][dd][t4], Cj + (size_t)((c0) + dd) * BT + bt0 + t4); } \
    _Pragma("unroll") for (int j2 = 0; j2 < 8; j2++) { int c4 = tid + j2*128; \
        int dd = c4 >> 5, cc = (c4 & 31) * 4; \
        cpa16(&Bs[bufi][dd][cc], Mb + (size_t)((c0) + dd) * CDD + cc); } \
    CP_COMMIT; } while (0)

__global__ void __launch_bounds__(128) k_corr(int j) {
    __shared__ __align__(16) float As[2][32][32];    // 8KB
    __shared__ __align__(16) float Bs[2][32][128];   // 32KB
    int bt0 = blockIdx.x * 32;
    int qp = j + 1 + blockIdx.y;
    int tid = threadIdx.x, txt = tid & 7, tyc = tid >> 3;
    const float* Cj = g_cT + (size_t)j * CDD * BT;
    const float* Mb = g_M + (size_t)(j * 8 + qp) * CDD * CDD;

    CORR_PREFETCH(0, 0);
    unsigned long long acc[8][2];
    #pragma unroll
    for (int i = 0; i < 8; i++) { acc[i][0] = 0ull; acc[i][1] = 0ull; }

    int buf = 0;
    for (int kt = 0; kt < 4; kt++) {
        CP_WAIT0; __syncthreads();
        if (kt + 1 < 4) CORR_PREFETCH(buf ^ 1, (kt + 1) * 32);
        #pragma unroll 8
        for (int dd = 0; dd < 32; dd++) {
            ulonglong2 v = *(const ulonglong2*)&As[buf][dd][txt * 4];
            float4 w0 = *(const float4*)&Bs[buf][dd][tyc * 8];
            float4 w1 = *(const float4*)&Bs[buf][dd][tyc * 8 + 4];
            MICRO4x8(w0, w1);
        }
        buf ^= 1;
    }
    #pragma unroll
    for (int ci = 0; ci < 8; ci++) {
        int cp = tyc * 8 + ci;
        float2 u0 = unpk2(acc[ci][0]), u1 = unpk2(acc[ci][1]);
        float* hp = g_H + ((size_t)qp * CDD + cp) * BT + bt0 + txt * 4;
        float4 h = *(const float4*)hp;
        h.x -= u0.x; h.y -= u0.y; h.z -= u1.x; h.w -= u1.y;
        *(float4*)hp = h;
    }
}

// ---- final output: out[b][d][t] = sum_{q,c} cT[qc][bt]*Wout[qc][d] + sb[d] ----
// grid (16 tt, 8 dblk, 8 b), 256 thr. tile 128t x 128d, inner 1024, ktile 16.
__global__ void __launch_bounds__(256) k_out(const float* __restrict__ Wout,
                                             float* __restrict__ out) {
    __shared__ __align__(16) float As[2][16][128];   // [qc][t]
    __shared__ __align__(16) float Bs[2][16][128];   // [qc][d]
    int t0 = blockIdx.x * 128, d0 = blockIdx.y * 128, b = blockIdx.z;
    int tid = threadIdx.x, txt = tid & 15, tyc = tid >> 4;
    int bt0 = b * TQ + t0;
    const float* Wb = Wout + d0;

    #pragma unroll
    for (int j2 = 0; j2 < 2; j2++) { int c4 = tid + j2*256; int dd = c4 >> 5, x4 = (c4 & 31)*4;
        cpa16(&As[0][dd][x4], g_cT + (size_t)dd * BT + bt0 + x4);
        cpa16(&Bs[0][dd][x4], Wb + (size_t)dd * DIMM + x4); }
    CP_COMMIT;

    unsigned long long acc[8][4];
    #pragma unroll
    for (int i = 0; i < 8; i++)
        #pragma unroll
        for (int p = 0; p < 4; p++) acc[i][p] = 0ull;

    int buf = 0;
    for (int s = 0; s < 64; s++) {
        CP_WAIT0; __syncthreads();
        if (s + 1 < 64) { int qc0 = (s + 1) * 16, nb = buf ^ 1;
            #pragma unroll
            for (int j2 = 0; j2 < 2; j2++) { int c4 = tid + j2*256; int dd = c4 >> 5, x4 = (c4 & 31)*4;
                cpa16(&As[nb][dd][x4], g_cT + (size_t)(qc0 + dd) * BT + bt0 + x4);
                cpa16(&Bs[nb][dd][x4], Wb + (size_t)(qc0 + dd) * DIMM + x4); }
            CP_COMMIT; }
        #pragma unroll
        for (int dd = 0; dd < 16; dd++) {
            ulonglong2 v0 = *(const ulonglong2*)&As[buf][dd][txt * 8];
            ulonglong2 v1 = *(const ulonglong2*)&As[buf][dd][txt * 8 + 4];
            float4 w0 = *(const float4*)&Bs[buf][dd][tyc * 8];
            float4 w1 = *(const float4*)&Bs[buf][dd][tyc * 8 + 4];
            MICRO8(w0, w1);
        }
        buf ^= 1;
    }
    #pragma unroll
    for (int ci = 0; ci < 8; ci++) {
        int d = d0 + tyc * 8 + ci;
        float sb = g_sb[d];
        float2 u0 = unpk2(acc[ci][0]), u1 = unpk2(acc[ci][1]);
        float2 u2 = unpk2(acc[ci][2]), u3 = unpk2(acc[ci][3]);
        float* op = out + ((size_t)b * DIMM + d) * TQ + t0 + txt * 8;
        *(float4*)op       = make_float4(u0.x + sb, u0.y + sb, u1.x + sb, u1.y + sb);
        *(float4*)(op + 4) = make_float4(u2.x + sb, u2.y + sb, u3.x + sb, u3.y + sb);
    }
}

extern "C" void kernel_launch(void* const* d_in, const int* in_sizes, int n_in,
                              void* d_out, int out_size) {
    const float* emb  = (const float*)d_in[0];
    const float* Win  = (const float*)d_in[1];
    const float* bin  = (const float*)d_in[2];
    const float* Wout = (const float*)d_in[3];
    const float* bout = (const float*)d_in[4];
    const float* E    = (const float*)d_in[5];
    float* out = (float*)d_out;

    // precompute (parallel, outside the sequential chain)
    k_et<<<dim3(KK / 32, CDD / 32, QQ), 256>>>(E);
    k_e2<<<(QQ * KK) / 8, 256>>>(E);
    k_woT<<<dim3(DIMM / 32, CDD / 32, QQ), 256>>>(Wout);
    k_pb<<<DIMM / 256, 256>>>(bout);
    k_bv<<<QQ, CDD>>>(Win);
    k_Mp<<<dim3(QQ, QQ, 8), 256>>>(Win);
    k_Mred<<<(QQ*QQ*CDD*CDD/4) / 256, 256>>>();
    k_H0<<<dim3(TQ / 128, BB, QQ), 256>>>(emb, Win, bin);

    // sequential chain: dist -> gather -> low-rank correction of future h's
    for (int q = 0; q < QQ; q++) {
        k_dist<<<dim3(BT / 64, 4), 128>>>(q);
        k_gather<<<BT / 64, 128>>>(E, q);
        if (q < QQ - 1) k_corr<<<dim3(BT / 32, QQ - 1 - q), 128>>>(q);
    }

    // one big batched decode GEMM at the end
    k_out<<<dim3(TQ / 128, DIMM / 128, BB), 256>>>(Wout, out);
}

// round 13
// speedup vs baseline: 1.0719x; 1.0719x over previous
#include <cuda_runtime.h>

#define BB   8
#define DIMM 1024
#define TQ   2048
#define CDD  128
#define KK   1024
#define QQ   8
#define BT   (BB*TQ)   // 16384

// ---- scratch (device globals) ----
__device__ float g_resid[BB*DIMM*TQ];            // 64 MB residual [b][d][t]
__device__ float g_hp[2][CDD*BT];                // 16 MB h partials (d-split halves) [c][bt]
__device__ float g_cT[CDD*BT];                   // 8 MB gathered codes [c][bt]
__device__ float g_et[QQ*CDD*KK];                // 4 MB E transposed [q][c][k]
__device__ unsigned long long g_part[4*BT];      // per-split argmin packs
__device__ float g_e2[QQ*KK];                    // ||E_k||^2

// ---- packed f32x2 helpers ----
static __device__ __forceinline__ unsigned long long pk2(float v) {
    unsigned long long r; unsigned int u = __float_as_uint(v);
    asm("mov.b64 %0, {%1, %1};" : "=l"(r) : "r"(u));
    return r;
}
static __device__ __forceinline__ void fma2(unsigned long long& d,
                                            unsigned long long a, unsigned long long b) {
    asm("fma.rn.f32x2 %0, %1, %2, %0;" : "+l"(d) : "l"(a), "l"(b));
}
static __device__ __forceinline__ float2 unpk2(unsigned long long v) {
    unsigned int lo, hi;
    asm("mov.b64 {%0, %1}, %2;" : "=r"(lo), "=r"(hi) : "l"(v));
    float2 f; f.x = __uint_as_float(lo); f.y = __uint_as_float(hi);
    return f;
}
static __device__ __forceinline__ void cpa16(void* s, const void* g) {
    unsigned int sa = (unsigned int)__cvta_generic_to_shared(s);
    asm volatile("cp.async.cg.shared.global [%0], [%1], 16;" :: "r"(sa), "l"(g));
}
#define CP_COMMIT asm volatile("cp.async.commit_group;")
#define CP_WAIT0  asm volatile("cp.async.wait_group 0;")

// 8 scalar rows (S0,S1 float4) x 8 packed lanes (v0,v1 ulonglong2) -> 32 FFMA2
#define FMA2_ROW(i, s) { unsigned long long p = pk2(s); \
    fma2(acc[i][0], p, v0.x); fma2(acc[i][1], p, v0.y); \
    fma2(acc[i][2], p, v1.x); fma2(acc[i][3], p, v1.y); }
#define MICRO8(S0, S1) do { \
    FMA2_ROW(0, S0.x); FMA2_ROW(1, S0.y); FMA2_ROW(2, S0.z); FMA2_ROW(3, S0.w); \
    FMA2_ROW(4, S1.x); FMA2_ROW(5, S1.y); FMA2_ROW(6, S1.z); FMA2_ROW(7, S1.w); } while (0)

// ---- per-code squared norms ----
__global__ void k_e2(const float* __restrict__ E) {
    int row  = blockIdx.x * (blockDim.x >> 5) + (threadIdx.x >> 5);
    int lane = threadIdx.x & 31;
    if (row >= QQ * KK) return;
    const float* e = E + (size_t)row * CDD;
    float4 v = *(const float4*)(e + lane * 4);
    float s = v.x*v.x + v.y*v.y + v.z*v.z + v.w*v.w;
    #pragma unroll
    for (int o = 16; o; o >>= 1) s += __shfl_xor_sync(0xffffffffu, s, o);
    if (lane == 0) g_e2[row] = s;
}

// ---- E transpose: g_et[q][c][k] = E[q][k][c] ----
__global__ void k_et(const float* __restrict__ E) {
    __shared__ float tile[32][33];
    int q = blockIdx.z, k0 = blockIdx.x * 32, c0 = blockIdx.y * 32;
    int tx = threadIdx.x & 31, ty = threadIdx.x >> 5;
    const float* Eq = E + (size_t)q * KK * CDD;
    #pragma unroll
    for (int i = 0; i < 4; i++)
        tile[ty + 8*i][tx] = Eq[(size_t)(k0 + ty + 8*i) * CDD + c0 + tx];
    __syncthreads();
    float* o = g_et + (size_t)q * CDD * KK;
    #pragma unroll
    for (int i = 0; i < 4; i++)
        o[(size_t)(c0 + ty + 8*i) * KK + k0 + tx] = tile[tx][ty + 8*i];
}

// ---- kernel 1: h partial: g_hp[ds][c][bt] = sum_{d in half ds} src[b,d,t]*Win[d,c] ----
// grid (32 t-tiles, 8 b, 2 d-halves), 128 thr. tile 64t x 128c, ktile 16, micro 8t x 8c.
#define PROJ_PREFETCH(bufi, d0) do { \
    _Pragma("unroll") for (int j = 0; j < 2; j++) { int ix = tid + j*128; \
        int dd = ix >> 4, t4 = (ix & 15) * 4; \
        cpa16(&As[bufi][dd][t4], rb + (size_t)((d0) + dd) * TQ + t4); } \
    _Pragma("unroll") for (int j = 0; j < 4; j++) { int ix = tid + j*128; \
        int dd = ix >> 5, cc = (ix & 31) * 4; \
        cpa16(&Bs[bufi][dd][cc], Wq + (size_t)((d0) + dd) * CDD + cc); } \
    CP_COMMIT; } while (0)

__global__ void __launch_bounds__(128) k_proj(const float* __restrict__ emb,
                                              const float* __restrict__ Win,
                                              int q, int use_emb) {
    __shared__ __align__(16) float As[2][16][64];    // [d][t] 8KB
    __shared__ __align__(16) float Bs[2][16][128];   // [d][c] 16KB
    int t0 = blockIdx.x * 64, b = blockIdx.y, ds = blockIdx.z;
    int tid = threadIdx.x, txt = tid & 7, tyc = tid >> 3;  // t = txt*8, c = tyc*8
    int bt0 = b * TQ + t0;
    const float* src = use_emb ? emb : (const float*)g_resid;   // device-side symbol!
    const float* rb = src + (size_t)b * DIMM * TQ + (size_t)ds * 512 * TQ + t0;
    const float* Wq = Win + (size_t)q * DIMM * CDD + (size_t)ds * 512 * CDD;

    PROJ_PREFETCH(0, 0);
    unsigned long long acc[8][4];
    #pragma unroll
    for (int i = 0; i < 8; i++)
        #pragma unroll
        for (int p = 0; p < 4; p++) acc[i][p] = 0ull;

    int buf = 0;
    for (int kt = 0; kt < 32; kt++) {
        CP_WAIT0; __syncthreads();
        if (kt + 1 < 32) PROJ_PREFETCH(buf ^ 1, (kt + 1) * 16);
        #pragma unroll
        for (int dd = 0; dd < 16; dd++) {
            ulonglong2 v0 = *(const ulonglong2*)&As[buf][dd][txt * 8];
            ulonglong2 v1 = *(const ulonglong2*)&As[buf][dd][txt * 8 + 4];
            float4 w0 = *(const float4*)&Bs[buf][dd][tyc * 8];
            float4 w1 = *(const float4*)&Bs[buf][dd][tyc * 8 + 4];
            MICRO8(w0, w1);
        }
        buf ^= 1;
    }
    float* hb = g_hp[ds];
    #pragma unroll
    for (int ci = 0; ci < 8; ci++) {
        int c = tyc * 8 + ci;
        float2 u0 = unpk2(acc[ci][0]), u1 = unpk2(acc[ci][1]);
        float2 u2 = unpk2(acc[ci][2]), u3 = unpk2(acc[ci][3]);
        float* hp = hb + (size_t)c * BT + bt0 + txt * 8;
        *(float4*)hp       = make_float4(u0.x, u0.y, u1.x, u1.y);
        *(float4*)(hp + 4) = make_float4(u2.x, u2.y, u3.x, u3.y);
    }
}

// ---- kernel 2: argmin_k ( e2[k] - 2 h.E_k ), 4-way code split ----
// grid (256, 4), 128 thr. 64 rows x 256 codes per block, micro 8t x 8k.
#define ES_PREFETCH(bufi, n0, c0) do { \
    _Pragma("unroll") for (int j = 0; j < 4; j++) { int ix = tid + j*128; \
        int cc = ix >> 5, kk = (ix & 31) * 4; \
        cpa16(&Es[bufi][cc][kk], etq + (size_t)((c0) + cc) * KK + (n0) + kk); } \
    CP_COMMIT; } while (0)

__global__ void __launch_bounds__(128) k_dist(const float* __restrict__ bin, int q) {
    __shared__ __align__(16) float hsT[128][64];    // 32KB
    __shared__ __align__(16) float Es[2][16][128];  // 16KB
    __shared__ unsigned long long red[64][16];      // 8KB
    int r0 = blockIdx.x * 64, nbase = blockIdx.y * 256;
    int tid = threadIdx.x, txt = tid & 7, tyk = tid >> 3;
    const float* etq = g_et + (size_t)q * CDD * KK;
    const float* e2q = g_e2 + q * KK;
    const float* binq = bin + q * CDD;

    ES_PREFETCH(0, nbase, 0);
    float e2r[2][8];
    #pragma unroll
    for (int nt = 0; nt < 2; nt++) {
        float4 a = *(const float4*)(e2q + nbase + nt * 128 + tyk * 8);
        float4 c = *(const float4*)(e2q + nbase + nt * 128 + tyk * 8 + 4);
        e2r[nt][0] = a.x; e2r[nt][1] = a.y; e2r[nt][2] = a.z; e2r[nt][3] = a.w;
        e2r[nt][4] = c.x; e2r[nt][5] = c.y; e2r[nt][6] = c.z; e2r[nt][7] = c.w;
    }
    // h = hp0 + hp1 + bin (merge d-split partials)
    const float* hp0 = g_hp[0];
    const float* hp1 = g_hp[1];
    #pragma unroll
    for (int j = 0; j < 16; j++) {
        int ix = tid + j * 128; int c = ix >> 4, t4 = (ix & 15) * 4;
        float4 a = *(const float4*)(hp0 + (size_t)c * BT + r0 + t4);
        float4 bq = *(const float4*)(hp1 + (size_t)c * BT + r0 + t4);
        float bi = binq[c];
        *(float4*)&hsT[c][t4] = make_float4(a.x + bq.x + bi, a.y + bq.y + bi,
                                            a.z + bq.z + bi, a.w + bq.w + bi);
    }

    float minv[8]; int mini[8];
    #pragma unroll
    for (int j = 0; j < 8; j++) { minv[j] = 3.0e38f; mini[j] = 0; }
    unsigned long long acc[8][4];
    int buf = 0;
    for (int s = 0; s < 16; s++) {      // 2 n-tiles x 8 c-chunks
        CP_WAIT0; __syncthreads();
        if (s + 1 < 16) { int s1 = s + 1;
            ES_PREFETCH(buf ^ 1, nbase + (s1 >> 3) * 128, (s1 & 7) * 16); }
        if ((s & 7) == 0) {
            #pragma unroll
            for (int i = 0; i < 8; i++)
                #pragma unroll
                for (int j = 0; j < 4; j++) acc[i][j] = 0ull;
        }
        int c0 = (s & 7) * 16;
        #pragma unroll 8
        for (int cc = 0; cc < 16; cc++) {
            ulonglong2 v0 = *(const ulonglong2*)&hsT[c0 + cc][txt * 8];
            ulonglong2 v1 = *(const ulonglong2*)&hsT[c0 + cc][txt * 8 + 4];
            float4 e0 = *(const float4*)&Es[buf][cc][tyk * 8];
            float4 e1 = *(const float4*)&Es[buf][cc][tyk * 8 + 4];
            MICRO8(e0, e1);
        }
        if ((s & 7) == 7) {
            int nt = s >> 3;
            int kb = nbase + nt * 128 + tyk * 8;
            #pragma unroll
            for (int ki = 0; ki < 8; ki++) {
                float ev = e2r[nt][ki];
                int k = kb + ki;
                #pragma unroll
                for (int tp = 0; tp < 4; tp++) {
                    float2 u = unpk2(acc[ki][tp]);
                    float da = ev - 2.0f * u.x;
                    float db = ev - 2.0f * u.y;
                    if (da < minv[tp*2])     { minv[tp*2]     = da; mini[tp*2]     = k; }
                    if (db < minv[tp*2 + 1]) { minv[tp*2 + 1] = db; mini[tp*2 + 1] = k; }
                }
            }
        }
        buf ^= 1;
    }
    #pragma unroll
    for (int j = 0; j < 8; j++) {
        unsigned int bbits = __float_as_uint(minv[j]);
        bbits = (bbits & 0x80000000u) ? ~bbits : (bbits | 0x80000000u);
        red[txt * 8 + j][tyk] = ((unsigned long long)bbits << 32) | (unsigned int)mini[j];
    }
    __syncthreads();
    if (tid < 64) {
        unsigned long long m = red[tid][0];
        #pragma unroll
        for (int x = 1; x < 16; x++) { unsigned long long v = red[tid][x]; if (v < m) m = v; }
        g_part[(size_t)blockIdx.y * BT + r0 + tid] = m;
    }
}

// ---- kernel 2.5: merge splits + gather: g_cT[c][bt] = E_q[idx[bt]][c] ----
__global__ void __launch_bounds__(128) k_gather(const float* __restrict__ E, int q) {
    __shared__ float sT[128][65];
    __shared__ int sidx[64];
    int bt0 = blockIdx.x * 64;
    int tid = threadIdx.x;
    if (tid < 64) {
        unsigned long long m = g_part[bt0 + tid];
        #pragma unroll
        for (int s = 1; s < 4; s++) {
            unsigned long long v = g_part[(size_t)s * BT + bt0 + tid];
            if (v < m) m = v;
        }
        sidx[tid] = (int)(unsigned int)(m & 0xFFFFFFFFull);
    }
    __syncthreads();
    const float* Eq = E + (size_t)q * KK * CDD;
    #pragma unroll
    for (int j = 0; j < 16; j++) {
        int ch = tid + j * 128; int tt = ch >> 5, c4 = ch & 31;
        float4 v = *(const float4*)(Eq + (size_t)sidx[tt] * CDD + c4 * 4);
        sT[c4*4][tt] = v.x; sT[c4*4+1][tt] = v.y; sT[c4*4+2][tt] = v.z; sT[c4*4+3][tt] = v.w;
    }
    __syncthreads();
    #pragma unroll
    for (int j = 0; j < 16; j++) {
        int ch = tid + j * 128; int c = ch >> 4, t4 = (ch & 15) * 4;
        *(float4*)(g_cT + (size_t)c * BT + bt0 + t4) =
            make_float4(sT[c][t4], sT[c][t4+1], sT[c][t4+2], sT[c][t4+3]);
    }
}

// ---- kernel 3: qv = g_cT.Wout + bout; resid update or final out ----
// grid (32 t-tiles, 8 d-blk, 8 b), 128 thr. tile 64t x 128d, ktile 16, micro 8t x 8d.
#define DEC_PREFETCH(bufi, c0) do { \
    _Pragma("unroll") for (int j = 0; j < 2; j++) { int ix = tid + j*128; \
        int cc = ix >> 4, t4 = (ix & 15) * 4; \
        cpa16(&As[bufi][cc][t4], g_cT + (size_t)((c0) + cc) * BT + bt0 + t4); } \
    _Pragma("unroll") for (int j = 0; j < 4; j++) { int ix = tid + j*128; \
        int cc = ix >> 5, d4 = (ix & 31) * 4; \
        cpa16(&Bs[bufi][cc][d4], Wq + (size_t)((c0) + cc) * DIMM + d4); } \
    CP_COMMIT; } while (0)

__global__ void __launch_bounds__(128) k_dec(const float* __restrict__ Wout,
                                             const float* __restrict__ bout, int q,
                                             const float* __restrict__ emb,
                                             float* __restrict__ out,
                                             int use_emb, int is_final) {
    __shared__ __align__(16) float As[2][16][64];    // [c][t] 8KB
    __shared__ __align__(16) float Bs[2][16][128];   // [c][d] 16KB
    int t0 = blockIdx.x * 64, d0 = blockIdx.y * 128, b = blockIdx.z;
    int tid = threadIdx.x, txt = tid & 7, tyd = tid >> 3;
    int bt0 = b * TQ + t0;
    const float* rsrc = use_emb ? emb : (const float*)g_resid;   // device-side symbol!
    const float* Wq = Wout + (size_t)q * CDD * DIMM + d0;

    DEC_PREFETCH(0, 0);
    unsigned long long acc[8][4];
    #pragma unroll
    for (int i = 0; i < 8; i++)
        #pragma unroll
        for (int p = 0; p < 4; p++) acc[i][p] = 0ull;

    int buf = 0;
    for (int kt = 0; kt < 8; kt++) {
        CP_WAIT0; __syncthreads();
        if (kt + 1 < 8) DEC_PREFETCH(buf ^ 1, (kt + 1) * 16);
        #pragma unroll
        for (int cc = 0; cc < 16; cc++) {
            ulonglong2 v0 = *(const ulonglong2*)&As[buf][cc][txt * 8];
            ulonglong2 v1 = *(const ulonglong2*)&As[buf][cc][txt * 8 + 4];
            float4 w0 = *(const float4*)&Bs[buf][cc][tyd * 8];
            float4 w1 = *(const float4*)&Bs[buf][cc][tyd * 8 + 4];
            MICRO8(w0, w1);
        }
        buf ^= 1;
    }
    #pragma unroll
    for (int di = 0; di < 8; di++) {
        int d = d0 + tyd * 8 + di;
        float bo = bout[q * DIMM + d];
        float2 u0 = unpk2(acc[di][0]), u1 = unpk2(acc[di][1]);
        float2 u2 = unpk2(acc[di][2]), u3 = unpk2(acc[di][3]);
        size_t off = ((size_t)b * DIMM + d) * TQ + t0 + txt * 8;
        float4 q0 = make_float4(u0.x + bo, u0.y + bo, u1.x + bo, u1.y + bo);
        float4 q1 = make_float4(u2.x + bo, u2.y + bo, u3.x + bo, u3.y + bo);
        float4 r0v = *(const float4*)(rsrc + off);
        float4 r1v = *(const float4*)(rsrc + off + 4);
        if (is_final) {   // out = emb - resid + qv
            float4 e0 = *(const float4*)(emb + off);
            float4 e1 = *(const float4*)(emb + off + 4);
            *(float4*)(out + off)     = make_float4(e0.x - r0v.x + q0.x, e0.y - r0v.y + q0.y,
                                                    e0.z - r0v.z + q0.z, e0.w - r0v.w + q0.w);
            *(float4*)(out + off + 4) = make_float4(e1.x - r1v.x + q1.x, e1.y - r1v.y + q1.y,
                                                    e1.z - r1v.z + q1.z, e1.w - r1v.w + q1.w);
        } else {          // resid = rsrc - qv
            *(float4*)(g_resid + off)     = make_float4(r0v.x - q0.x, r0v.y - q0.y,
                                                        r0v.z - q0.z, r0v.w - q0.w);
            *(float4*)(g_resid + off + 4) = make_float4(r1v.x - q1.x, r1v.y - q1.y,
                                                        r1v.z - q1.z, r1v.w - q1.w);
        }
    }
}

extern "C" void kernel_launch(void* const* d_in, const int* in_sizes, int n_in,
                              void* d_out, int out_size) {
    const float* emb  = (const float*)d_in[0];
    const float* Win  = (const float*)d_in[1];
    const float* bin  = (const float*)d_in[2];
    const float* Wout = (const float*)d_in[3];
    const float* bout = (const float*)d_in[4];
    const float* E    = (const float*)d_in[5];
    float* out = (float*)d_out;

    k_et<<<dim3(KK / 32, CDD / 32, QQ), 256>>>(E);
    k_e2<<<(QQ * KK) / 8, 256>>>(E);
    for (int q = 0; q < QQ; q++) {
        int use_emb = (q == 0) ? 1 : 0;
        k_proj<<<dim3(TQ / 64, BB, 2), 128>>>(emb, Win, q, use_emb);
        k_dist<<<dim3(BT / 64, 4), 128>>>(bin, q);
        k_gather<<<BT / 64, 128>>>(E, q);
        k_dec<<<dim3(TQ / 64, DIMM / 128, BB), 128>>>(
            Wout, bout, q, emb, out, use_emb, (q == QQ - 1) ? 1 : 0);
    }
}